// round 5
// baseline (speedup 1.0000x reference)
#include <cuda_runtime.h>
#include <math.h>

#define TT    64
#define BATCH 4096
#define HID   256
#define BB    16
#define SSTR  260
#define NCTA  256

// Raw per-step outputs: [cta][t][b_local][c] with c = {spk0, spk1, mem0, mem1}.
__device__ float g_vals[NCTA * TT * BB * 4];

__device__ __forceinline__ float clamp01(float v) {
    return fminf(fmaxf(v, 0.0f), 1.0f);
}

// One LIF layer, numerics matched to reference fp32 codegen:
//   dot = ascending-j single FMA chain from 0 (cublas/Eigen order)
//   cur = dot + bias                           (separate rounded add)
//   mem = fma(beta, mem, cur) - reset*thr      (XLA contracts mul+add -> FMA)
__device__ __forceinline__ void gemv_lif_seq(
    const float* __restrict__ Wrow,   // this thread's weight row (256 floats)
    const float* __restrict__ Sin,    // smem spikes [BB][SSTR]
    float*       __restrict__ Sout,   // smem spikes [BB][SSTR]
    float bias, float beta, float thr,
    float* m, int h)
{
    float acc[BB];
    #pragma unroll
    for (int b = 0; b < BB; b++) acc[b] = 0.0f;

    #pragma unroll 2
    for (int j = 0; j < HID / 4; j++) {
        float4 w = *(const float4*)(Wrow + 4 * j);
        #pragma unroll
        for (int b = 0; b < BB; b++) {
            float4 s = *(const float4*)(Sin + b * SSTR + 4 * j);
            acc[b] = fmaf(s.x, w.x, acc[b]);
            acc[b] = fmaf(s.y, w.y, acc[b]);
            acc[b] = fmaf(s.z, w.z, acc[b]);
            acc[b] = fmaf(s.w, w.w, acc[b]);
        }
    }

    #pragma unroll
    for (int b = 0; b < BB; b++) {
        float cur = __fadd_rn(acc[b], bias);
        float rst = (__fsub_rn(m[b], thr) > 0.0f) ? thr : 0.0f;
        m[b] = __fsub_rn(fmaf(beta, m[b], cur), rst);
        Sout[b * SSTR + h] = (__fsub_rn(m[b], thr) > 0.0f) ? 1.0f : 0.0f;
    }
}

__global__ __launch_bounds__(256, 2) void snn_main(
    const float* __restrict__ x,
    const float* __restrict__ W_in,  const float* __restrict__ b_in,
    const float* __restrict__ beta_in, const float* __restrict__ thr_in,
    const float* __restrict__ W_h,   const float* __restrict__ b_h,
    const float* __restrict__ beta_h,  const float* __restrict__ thr_h,
    const float* __restrict__ W_h2,  const float* __restrict__ b_h2,
    const float* __restrict__ beta_h2, const float* __restrict__ thr_h2,
    const float* __restrict__ W_out, const float* __restrict__ b_out,
    const float* __restrict__ beta_out)
{
    __shared__ float SA[BB * SSTR];   // s1 / s4 (lifetimes disjoint)
    __shared__ float SB[BB * SSTR];   // s2
    __shared__ float xs[BB * 3];
    __shared__ float embs[TT];

    const int tid = threadIdx.x;
    const int h   = tid;
    const int cta = blockIdx.x;
    const int b0  = cta * BB;

    // Gaussian temporal embedding in double, identical op sequence to numpy
    if (tid < TT) {
        double z  = (tid - 32.0) / 6.4;
        double e  = exp(-0.5 * (z * z));
        double e0 = exp(-12.5);          // e.min() at pos=0 (z = -5.0 exactly)
        embs[tid] = (float)((e - e0) / (1.0 - e0));
    }

    const float win0 = W_in[h * 3 + 0], win1 = W_in[h * 3 + 1], win2 = W_in[h * 3 + 2];
    const float bin = b_in[h],  bt1 = clamp01(beta_in[h]),  th1 = thr_in[h];
    const float bh  = b_h[h],   bt2 = clamp01(beta_h[h]),   th2 = thr_h[h];
    const float bhh = b_h2[h],  bt3 = clamp01(beta_h2[h]),  th3 = thr_h2[h];

    float m1[BB], m2[BB], m4[BB];
    #pragma unroll
    for (int b = 0; b < BB; b++) { m1[b] = 0.0f; m2[b] = 0.0f; m4[b] = 0.0f; }

    // Output LI layer: warp 0, lane (b = tid>>1, o = tid&1) owns m3[b][o]
    float m3 = 0.0f, btO = 0.0f, bO = 0.0f;
    const int ob = tid >> 1, oo = tid & 1;
    if (tid < 32) { btO = clamp01(beta_out[oo]); bO = b_out[oo]; }

    const float* WhRow  = W_h  + h * HID;
    const float* Wh2Row = W_h2 + h * HID;

    __syncthreads();

    for (int t = 0; t < TT; t++) {
        // Temporally-weighted inputs for this CTA's 16 batches
        if (tid < BB * 3) {
            xs[tid] = __fmul_rn(x[(t * BATCH + b0) * 3 + tid], embs[t]);
        }
        __syncthreads();

        // Layer 1 (3 -> H): ascending-k chain from 0, bias after, fma membrane
        #pragma unroll
        for (int b = 0; b < BB; b++) {
            float d = fmaf(xs[b * 3 + 0], win0, 0.0f);
            d = fmaf(xs[b * 3 + 1], win1, d);
            d = fmaf(xs[b * 3 + 2], win2, d);
            float cur = __fadd_rn(d, bin);
            float rst = (__fsub_rn(m1[b], th1) > 0.0f) ? th1 : 0.0f;
            m1[b] = __fsub_rn(fmaf(bt1, m1[b], cur), rst);
            SA[b * SSTR + h] = (__fsub_rn(m1[b], th1) > 0.0f) ? 1.0f : 0.0f;
        }
        __syncthreads();

        // Layer 2: s2 = LIF(W_h @ s1)
        gemv_lif_seq(WhRow, SA, SB, bh, bt2, th2, m2, h);
        __syncthreads();

        // Layer 3: s4 = LIF(W_h2 @ s2)
        gemv_lif_seq(Wh2Row, SB, SA, bhh, bt3, th3, m4, h);
        __syncthreads();

        // Output LI layer (warp 0): dot in exact ascending-k order,
        // m3 = fma(beta, m3, dot) + b_out   (contracted like XLA codegen)
        if (tid < 32) {
            const float* wrow = W_out + oo * HID;
            const float* srow = SA + ob * SSTR;
            float dot = 0.0f;
            #pragma unroll 8
            for (int hh = 0; hh < HID; hh++)
                dot = fmaf(srow[hh], wrow[hh], dot);
            m3 = __fadd_rn(fmaf(btO, m3, dot), bO);
            float spk = (__fsub_rn(m3, 1.0f) > 0.0f) ? 1.0f : 0.0f;

            float* dst = g_vals + ((cta * TT + t) * BB + ob) * 4;
            dst[oo]     = spk;
            dst[2 + oo] = m3;
        }
        __syncthreads();
    }
}

// Final contraction: out[r][o] = sum_k reshaped[r][k] * W_pred[o][k] + b_pred[o]
// in exact ascending-k order. r = t*64 + g; k = 4*(b%64) + c.
__global__ void snn_finalize(const float* __restrict__ W_pred,
                             const float* __restrict__ b_pred,
                             float* __restrict__ out)
{
    int idx = blockIdx.x * blockDim.x + threadIdx.x;
    if (idx >= BATCH * 2) return;
    int r = idx >> 1, o = idx & 1;
    int t = r >> 6, g = r & 63;

    const float* wp = W_pred + o * (TT * 4);
    float acc = 0.0f;
    #pragma unroll 4
    for (int k = 0; k < TT * 4; k++) {
        float v = g_vals[(g * 4 + (k >> 6)) * (TT * 64) + t * 64 + (k & 63)];
        acc = fmaf(v, wp[k], acc);
    }
    out[idx] = __fadd_rn(acc, b_pred[o]);
}

extern "C" void kernel_launch(void* const* d_in, const int* in_sizes, int n_in,
                              void* d_out, int out_size)
{
    const float* x        = (const float*)d_in[0];
    const float* W_in     = (const float*)d_in[1];
    const float* b_in     = (const float*)d_in[2];
    const float* beta_in  = (const float*)d_in[3];
    const float* thr_in   = (const float*)d_in[4];
    const float* W_h      = (const float*)d_in[5];
    const float* b_h      = (const float*)d_in[6];
    const float* beta_h   = (const float*)d_in[7];
    const float* thr_h    = (const float*)d_in[8];
    const float* W_h2     = (const float*)d_in[9];
    const float* b_h2     = (const float*)d_in[10];
    const float* beta_h2  = (const float*)d_in[11];
    const float* thr_h2   = (const float*)d_in[12];
    const float* W_out    = (const float*)d_in[13];
    const float* b_out    = (const float*)d_in[14];
    const float* beta_out = (const float*)d_in[15];
    const float* W_pred   = (const float*)d_in[16];
    const float* b_pred   = (const float*)d_in[17];
    float* out = (float*)d_out;

    snn_main<<<NCTA, 256>>>(x, W_in, b_in, beta_in, thr_in,
                            W_h, b_h, beta_h, thr_h,
                            W_h2, b_h2, beta_h2, thr_h2,
                            W_out, b_out, beta_out);
    snn_finalize<<<32, 256>>>(W_pred, b_pred, out);
}